// round 16
// baseline (speedup 1.0000x reference)
#include <cuda_runtime.h>
#include <math.h>

#define NQB 4
#define BB  512
#define SS  256
#define DD  64
#define HH  128
#define FULL 0xffffffffu

#define YSCALE  4194304.0f             // 2^22
#define YINV    (1.0f / 4194304.0f)
#define ZINV    (1.0f / 67108864.0f)   // 2^-26 (amp carries 2^13 via zx init)

__device__ __forceinline__ float2 cmul(float2 a, float2 b) {
    return make_float2(fmaf(a.x, b.x, -a.y * b.y), fmaf(a.x, b.y, a.y * b.x));
}
__device__ __forceinline__ float tanha(float x) {
    float r;
    asm("tanh.approx.f32 %0, %1;" : "=f"(r) : "f"(x));
    return r;
}
// warp-wide s32 add reduction (sm_80+), result in all lanes
__device__ __forceinline__ int redux_add_s32(int v) {
    int r;
    asm("redux.sync.add.s32 %0, %1, 0xffffffff;" : "=r"(r) : "r"(v));
    return r;
}

// source index after the CNOT ring (0,1)(1,2)(2,3)(3,0), gather form
__device__ __forceinline__ int cnot_src(int i) {
    i ^= (i & 1) ? 8 : 0;   // CNOT(3,0)
    i ^= (i & 2) ? 1 : 0;   // CNOT(2,3)
    i ^= (i & 4) ? 2 : 0;   // CNOT(1,2)
    i ^= (i & 8) ? 4 : 0;   // CNOT(0,1)
    return i;
}

__global__ __launch_bounds__(128)
void qlstm_kernel(const float* __restrict__ x,
                  const float* __restrict__ W_in,
                  const float* __restrict__ b_in,
                  const float* __restrict__ W_out,
                  const float* __restrict__ b_out,
                  const float* __restrict__ w_f,
                  const float* __restrict__ w_i,
                  const float* __restrict__ w_u,
                  const float* __restrict__ w_o,
                  float* __restrict__ out,
                  int write_tails)
{
    __shared__ __align__(16) int4  sP[4];      // [warp] y partials (2^22 fixed-point)
    __shared__ __align__(16) float sZ[4][4];   // [gate][qubit] <Z_q>

    const int tid  = threadIdx.x;
    const int lane = tid & 31;
    const int wid  = tid >> 5;
    const int il   = lane & 15;         // amplitude index within half
    const int half = lane >> 4;         // which gate of the active pair
    const int b    = blockIdx.x;

    // VQC work assignment: even CTAs -> warps 0,1 active; odd CTAs -> warps 2,3.
    // Active warp `a` simulates gate 2a in half 0 and gate 2a+1 in half 1.
    const int  aw         = (b & 1) ? (wid - 2) : wid;
    const bool vqc_active = (unsigned)aw < 2u;
    const int  gate       = 2 * aw + half;        // valid only when vqc_active

    // ---- per-thread constants (registers) ----
    // W_in rows pre-scaled by 2^22 so accumulators are directly F2I-able
    float4 wi = *(const float4*)(W_in + 4 * tid);
    wi.x *= YSCALE; wi.y *= YSCALE; wi.z *= YSCALE; wi.w *= YSCALE;
    float4 wx = make_float4(0.f, 0.f, 0.f, 0.f);
    if (tid < DD) {
        wx = *(const float4*)(W_in + 4 * (HH + tid));
        wx.x *= YSCALE; wx.y *= YSCALE; wx.z *= YSCALE; wx.w *= YSCALE;
    }
    float4 binv = *(const float4*)(b_in);
    // wo scaled by 0.5 (tanh half-angle trick) * 2^-26 (z fixed-point)
    const float ws = 0.5f * ZINV;
    float wo0 = ws * W_out[tid];
    float wo1 = ws * W_out[HH + tid];
    float wo2 = ws * W_out[2 * HH + tid];
    float wo3 = ws * W_out[3 * HH + tid];
    float bo  = 0.5f * b_out[tid];

    bool  hq[NQB];
    float hs[NQB];
    #pragma unroll
    for (int q = 0; q < NQB; ++q) {
        hq[q] = (il >> (3 - q)) & 1;
        hs[q] = hq[q] ? 0.5f : -0.5f;
    }

    // fused ansatz U = RZ*RY*RX for this lane's gate (active warps only).
    // g0v0/g0v1: gate-0 row (applied to gathered lo/hi pair).
    // AA[q]/PB[q] for q=1..3: coefficient of OWN amp / PARTNER amp (no selects).
    float2 g0v0, g0v1, AA[NQB], PB[NQB];
    if (vqc_active) {
        const float* wg = (gate == 0) ? w_f : (gate == 1) ? w_i : (gate == 2) ? w_u : w_o;
        #pragma unroll
        for (int q = 0; q < NQB; ++q) {
            float sa, ca, sb, cb, sg, cg;
            sincosf(wg[q]           * 0.5f, &sa, &ca);
            sincosf(wg[NQB + q]     * 0.5f, &sb, &cb);
            sincosf(wg[2 * NQB + q] * 0.5f, &sg, &cg);
            float2 m00 = make_float2( cb * ca,  sb * sa);
            float2 m01 = make_float2(-sb * ca, -cb * sa);
            float2 m10 = make_float2( sb * ca, -cb * sa);
            float2 m11 = make_float2( cb * ca, -sb * sa);
            float2 e0  = make_float2(cg, -sg);
            float2 e1  = make_float2(cg,  sg);
            float2 u00 = cmul(e0, m00), u01 = cmul(e0, m01);
            float2 u10 = cmul(e1, m10), u11 = cmul(e1, m11);
            if (q == 0) {
                if (hq[0]) { g0v0 = u10; g0v1 = u11; }
                else       { g0v0 = u00; g0v1 = u01; }
            } else {
                if (hq[q]) { AA[q] = u11; PB[q] = u10; }   // own = hi amp
                else       { AA[q] = u00; PB[q] = u01; }   // own = lo amp
            }
        }
    }

    const int src0 = cnot_src(il & 7);   // bit8=0 partner, CNOT-ring fused
    const int src1 = cnot_src(il | 8);   // bit8=1 partner

    const float* xb = x + (size_t)b * SS * DD;
    float xv = (tid < DD) ? xb[tid] : 0.f;

    float h = 0.f, c = 0.f;
    float* op = out + (size_t)b * SS * HH + tid;

    for (int t = 0; t < SS; ++t) {
        // ---- 1. y = [h, x_t] @ W_in + b_in (fixed-point redux, all warps) ----
        float p0 = fmaf(h, wi.x, xv * wx.x);       // weights pre-scaled by 2^22
        float p1 = fmaf(h, wi.y, xv * wx.y);
        float p2 = fmaf(h, wi.z, xv * wx.z);
        float p3 = fmaf(h, wi.w, xv * wx.w);
        if (tid < DD && t + 1 < SS) xv = xb[(t + 1) * DD + tid];   // prefetch

        int i0 = redux_add_s32(__float2int_rn(p0));
        int i1 = redux_add_s32(__float2int_rn(p1));
        int i2 = redux_add_s32(__float2int_rn(p2));
        int i3 = redux_add_s32(__float2int_rn(p3));
        if (lane == 0) sP[wid] = make_int4(i0, i1, i2, i3);
        __syncthreads();

        // ---- 2-4: VQC, only the active warp pair ----
        if (vqc_active) {
            int4 q0 = sP[0], q1 = sP[1], q2 = sP[2], q3 = sP[3];
            float yv[NQB];
            yv[0] = fmaf(__int2float_rn(q0.x + q1.x + q2.x + q3.x), YINV, binv.x);
            yv[1] = fmaf(__int2float_rn(q0.y + q1.y + q2.y + q3.y), YINV, binv.y);
            yv[2] = fmaf(__int2float_rn(q0.z + q1.z + q2.z + q3.z), YINV, binv.z);
            yv[3] = fmaf(__int2float_rn(q0.w + q1.w + q2.w + q3.w), YINV, binv.w);

            // encoding product state; zx starts at 2^13 so |amp|^2 is 2^26 fixed-point
            float2 amp;
            {
                float P = 1.f, Dm = 1.f;
                float zx = 8192.f, zy = 0.f;
                #pragma unroll
                for (int q = 0; q < NQB; ++q) {
                    float y  = yv[q];
                    float t2 = y * y;
                    float r  = rsqrtf(1.f + t2);             // MUFU
                    float s  = y * r;                        // sin(atan y)
                    float x2 = fmaf(hs[q], s, 0.5f);
                    P *= x2;
                    float tq = hq[q] ? t2 : 0.f;
                    float nzx = fmaf(-zy, tq, zx);
                    float nzy = fmaf( zx, tq, zy);
                    zx = nzx; zy = nzy;
                    Dm *= fmaf(tq, tq, 1.f);
                }
                float m = P * rsqrtf(P * Dm);                // sqrt(P/D), 1 MUFU
                amp = make_float2(zx * m, zy * m);
            }

            // ansatz gate 0 fused with CNOT ring permutation
            float2 a0, a1;
            a0.x = __shfl_sync(FULL, amp.x, src0, 16);
            a0.y = __shfl_sync(FULL, amp.y, src0, 16);
            a1.x = __shfl_sync(FULL, amp.x, src1, 16);
            a1.y = __shfl_sync(FULL, amp.y, src1, 16);

            float2 cur;
            cur.x = g0v0.x*a0.x - g0v0.y*a0.y + g0v1.x*a1.x - g0v1.y*a1.y;
            cur.y = g0v0.x*a0.y + g0v0.y*a0.x + g0v1.x*a1.y + g0v1.y*a1.x;

            // gates 1..3: own/partner coefficient form, no selects
            #pragma unroll
            for (int q = 1; q < NQB; ++q) {
                const int m = 8 >> q;
                float ox = __shfl_xor_sync(FULL, cur.x, m, 16);
                float oy = __shfl_xor_sync(FULL, cur.y, m, 16);
                float2 A = AA[q], B = PB[q];
                float nx = A.x*cur.x - A.y*cur.y + B.x*ox - B.y*oy;
                float ny = A.x*cur.y + A.y*cur.x + B.x*oy + B.y*ox;
                cur.x = nx; cur.y = ny;
            }

            // <Z_q> via masked signed redux: half 0 feeds gate 2a, half 1 gate 2a+1
            float p = cur.x * cur.x + cur.y * cur.y;     // 2^26 fixed-point
            int ip = __float2int_rn(p);
            int in = -ip;
            int m0p = half ? 0 : ip, m0n = half ? 0 : in;
            int m1p = half ? ip : 0, m1n = half ? in : 0;
            int z00 = redux_add_s32((il & 8) ? m0n : m0p);
            int z01 = redux_add_s32((il & 4) ? m0n : m0p);
            int z02 = redux_add_s32((il & 2) ? m0n : m0p);
            int z03 = redux_add_s32((il & 1) ? m0n : m0p);
            int z10 = redux_add_s32((il & 8) ? m1n : m1p);
            int z11 = redux_add_s32((il & 4) ? m1n : m1p);
            int z12 = redux_add_s32((il & 2) ? m1n : m1p);
            int z13 = redux_add_s32((il & 1) ? m1n : m1p);
            if (lane == 0)
                *(float4*)sZ[gate] = make_float4(__int2float_rn(z00), __int2float_rn(z01),
                                                 __int2float_rn(z02), __int2float_rn(z03));
            else if (lane == 16)
                *(float4*)sZ[gate] = make_float4(__int2float_rn(z10), __int2float_rn(z11),
                                                 __int2float_rn(z12), __int2float_rn(z13));
        }
        __syncthreads();

        // ---- 5. projection + LSTM cell (one hidden dim per thread) ----
        float4 zf = *(const float4*)sZ[0];
        float4 zi = *(const float4*)sZ[1];
        float4 zu = *(const float4*)sZ[2];
        float4 zo = *(const float4*)sZ[3];
        float af = fmaf(zf.x, wo0, fmaf(zf.y, wo1, fmaf(zf.z, wo2, fmaf(zf.w, wo3, bo))));
        float ai = fmaf(zi.x, wo0, fmaf(zi.y, wo1, fmaf(zi.z, wo2, fmaf(zi.w, wo3, bo))));
        float ag = fmaf(zu.x, wo0, fmaf(zu.y, wo1, fmaf(zu.z, wo2, fmaf(zu.w, wo3, bo))));
        float ao = fmaf(zo.x, wo0, fmaf(zo.y, wo1, fmaf(zo.z, wo2, fmaf(zo.w, wo3, bo))));
        float f = fmaf(0.5f, tanha(af), 0.5f);
        float i = fmaf(0.5f, tanha(ai), 0.5f);
        float g = tanha(ag + ag);
        float o = fmaf(0.5f, tanha(ao), 0.5f);
        c = fmaf(f, c, i * g);
        h = o * tanha(c);

        *op = h;
        op += HH;
    }

    if (write_tails) {
        size_t base = (size_t)BB * SS * HH;
        out[base + (size_t)b * HH + tid] = h;
        out[base + (size_t)BB * HH + (size_t)b * HH + tid] = c;
    }
}

extern "C" void kernel_launch(void* const* d_in, const int* in_sizes, int n_in,
                              void* d_out, int out_size) {
    const float* x     = (const float*)d_in[0];
    const float* W_in  = (const float*)d_in[1];
    const float* b_in  = (const float*)d_in[2];
    const float* W_out = (const float*)d_in[3];
    const float* b_out = (const float*)d_in[4];
    const float* w_f   = (const float*)d_in[5];
    const float* w_i   = (const float*)d_in[6];
    const float* w_u   = (const float*)d_in[7];
    const float* w_o   = (const float*)d_in[8];
    float* out = (float*)d_out;

    int need_tail = (size_t)out_size >= (size_t)BB * SS * HH + 2 * (size_t)BB * HH;
    qlstm_kernel<<<BB, HH>>>(x, W_in, b_in, W_out, b_out,
                             w_f, w_i, w_u, w_o, out, need_tail);
}

// round 17
// speedup vs baseline: 1.1345x; 1.1345x over previous
#include <cuda_runtime.h>
#include <math.h>

#define NQB 4
#define BB  512
#define SS  256
#define DD  64
#define HH  128
#define FULL 0xffffffffu

#define YSCALE  4194304.0f             // 2^22
#define YINV    (1.0f / 4194304.0f)

__device__ __forceinline__ float2 cmul(float2 a, float2 b) {
    return make_float2(fmaf(a.x, b.x, -a.y * b.y), fmaf(a.x, b.y, a.y * b.x));
}
__device__ __forceinline__ float tanha(float x) {
    float r;
    asm("tanh.approx.f32 %0, %1;" : "=f"(r) : "f"(x));
    return r;
}
// warp-wide s32 add reduction (sm_80+), result in all lanes
__device__ __forceinline__ int redux_add_s32(int v) {
    int r;
    asm("redux.sync.add.s32 %0, %1, 0xffffffff;" : "=r"(r) : "r"(v));
    return r;
}

// source index after the CNOT ring (0,1)(1,2)(2,3)(3,0), gather form
__device__ __forceinline__ int cnot_src(int i) {
    i ^= (i & 1) ? 8 : 0;   // CNOT(3,0)
    i ^= (i & 2) ? 1 : 0;   // CNOT(2,3)
    i ^= (i & 4) ? 2 : 0;   // CNOT(1,2)
    i ^= (i & 8) ? 4 : 0;   // CNOT(0,1)
    return i;
}

__global__ __launch_bounds__(128)
void qlstm_kernel(const float* __restrict__ x,
                  const float* __restrict__ W_in,
                  const float* __restrict__ b_in,
                  const float* __restrict__ W_out,
                  const float* __restrict__ b_out,
                  const float* __restrict__ w_f,
                  const float* __restrict__ w_i,
                  const float* __restrict__ w_u,
                  const float* __restrict__ w_o,
                  float* __restrict__ out,
                  int write_tails)
{
    __shared__ __align__(16) int4  sP[4];      // [warp] y partials (2^22 fixed-point)
    __shared__ __align__(16) float sZ[4][4];   // [gate][qubit] <Z_q>

    const int tid  = threadIdx.x;
    const int lane = tid & 31;
    const int wid  = tid >> 5;
    const int il   = lane & 15;         // amplitude index within half
    const int half = lane >> 4;         // which gate of the active pair
    const int b    = blockIdx.x;

    // VQC work assignment: even CTAs -> warps 0,1 active; odd CTAs -> warps 2,3.
    // Active warp `a` simulates gate 2a in half 0 and gate 2a+1 in half 1.
    const int  aw         = (b & 1) ? (wid - 2) : wid;
    const bool vqc_active = (unsigned)aw < 2u;
    const int  gate       = 2 * aw + half;        // valid only when vqc_active

    // ---- per-thread constants (registers) ----
    // W_in rows pre-scaled by 2^22 so accumulators are directly F2I-able
    float4 wi = *(const float4*)(W_in + 4 * tid);
    wi.x *= YSCALE; wi.y *= YSCALE; wi.z *= YSCALE; wi.w *= YSCALE;
    float4 wx = make_float4(0.f, 0.f, 0.f, 0.f);
    if (tid < DD) {
        wx = *(const float4*)(W_in + 4 * (HH + tid));
        wx.x *= YSCALE; wx.y *= YSCALE; wx.z *= YSCALE; wx.w *= YSCALE;
    }
    float4 binv = *(const float4*)(b_in);
    // wo scaled by 0.5 (tanh half-angle trick)
    float wo0 = 0.5f * W_out[tid];
    float wo1 = 0.5f * W_out[HH + tid];
    float wo2 = 0.5f * W_out[2 * HH + tid];
    float wo3 = 0.5f * W_out[3 * HH + tid];
    float bo  = 0.5f * b_out[tid];

    bool  hq[NQB];
    float hs[NQB];
    #pragma unroll
    for (int q = 0; q < NQB; ++q) {
        hq[q] = (il >> (3 - q)) & 1;
        hs[q] = hq[q] ? 0.5f : -0.5f;
    }

    // fused ansatz U = RZ*RY*RX for this lane's gate (active warps only).
    // g0v0/g0v1: gate-0 row (applied to gathered lo/hi pair).
    // AA[q]/PB[q] for q=1..3: coefficient of OWN amp / PARTNER amp (no selects).
    float2 g0v0, g0v1, AA[NQB], PB[NQB];
    if (vqc_active) {
        const float* wg = (gate == 0) ? w_f : (gate == 1) ? w_i : (gate == 2) ? w_u : w_o;
        #pragma unroll
        for (int q = 0; q < NQB; ++q) {
            float sa, ca, sb, cb, sg, cg;
            sincosf(wg[q]           * 0.5f, &sa, &ca);
            sincosf(wg[NQB + q]     * 0.5f, &sb, &cb);
            sincosf(wg[2 * NQB + q] * 0.5f, &sg, &cg);
            float2 m00 = make_float2( cb * ca,  sb * sa);
            float2 m01 = make_float2(-sb * ca, -cb * sa);
            float2 m10 = make_float2( sb * ca, -cb * sa);
            float2 m11 = make_float2( cb * ca, -sb * sa);
            float2 e0  = make_float2(cg, -sg);
            float2 e1  = make_float2(cg,  sg);
            float2 u00 = cmul(e0, m00), u01 = cmul(e0, m01);
            float2 u10 = cmul(e1, m10), u11 = cmul(e1, m11);
            if (q == 0) {
                if (hq[0]) { g0v0 = u10; g0v1 = u11; }
                else       { g0v0 = u00; g0v1 = u01; }
            } else {
                if (hq[q]) { AA[q] = u11; PB[q] = u10; }   // own = hi amp
                else       { AA[q] = u00; PB[q] = u01; }   // own = lo amp
            }
        }
    }

    const int src0 = cnot_src(il & 7);   // bit8=0 partner, CNOT-ring fused
    const int src1 = cnot_src(il | 8);   // bit8=1 partner
    const bool isWriterZ = (__popc(il) == 1);     // both halves publish
    const int  zj        = 4 - __ffs(il);          // il 8->q0, 4->q1, 2->q2, 1->q3

    const float* xb = x + (size_t)b * SS * DD;
    float xv = (tid < DD) ? xb[tid] : 0.f;

    float h = 0.f, c = 0.f;
    float* op = out + (size_t)b * SS * HH + tid;

    for (int t = 0; t < SS; ++t) {
        // ---- 1. y = [h, x_t] @ W_in + b_in (fixed-point redux, all warps) ----
        float p0 = fmaf(h, wi.x, xv * wx.x);       // weights pre-scaled by 2^22
        float p1 = fmaf(h, wi.y, xv * wx.y);
        float p2 = fmaf(h, wi.z, xv * wx.z);
        float p3 = fmaf(h, wi.w, xv * wx.w);
        if (tid < DD && t + 1 < SS) xv = xb[(t + 1) * DD + tid];   // prefetch

        int i0 = redux_add_s32(__float2int_rn(p0));
        int i1 = redux_add_s32(__float2int_rn(p1));
        int i2 = redux_add_s32(__float2int_rn(p2));
        int i3 = redux_add_s32(__float2int_rn(p3));
        if (lane == 0) sP[wid] = make_int4(i0, i1, i2, i3);
        __syncthreads();

        // ---- 2-4: VQC, only the active warp pair ----
        if (vqc_active) {
            int4 q0 = sP[0], q1 = sP[1], q2 = sP[2], q3 = sP[3];
            float yv[NQB];
            yv[0] = fmaf(__int2float_rn(q0.x + q1.x + q2.x + q3.x), YINV, binv.x);
            yv[1] = fmaf(__int2float_rn(q0.y + q1.y + q2.y + q3.y), YINV, binv.y);
            yv[2] = fmaf(__int2float_rn(q0.z + q1.z + q2.z + q3.z), YINV, binv.z);
            yv[3] = fmaf(__int2float_rn(q0.w + q1.w + q2.w + q3.w), YINV, binv.w);

            // encoding product state, combined-normalization form
            float2 amp;
            {
                float P = 1.f, Dm = 1.f;
                float zx = 1.f, zy = 0.f;
                #pragma unroll
                for (int q = 0; q < NQB; ++q) {
                    float y  = yv[q];
                    float t2 = y * y;
                    float r  = rsqrtf(1.f + t2);             // MUFU
                    float s  = y * r;                        // sin(atan y)
                    float x2 = fmaf(hs[q], s, 0.5f);
                    P *= x2;
                    float tq = hq[q] ? t2 : 0.f;
                    float nzx = fmaf(-zy, tq, zx);
                    float nzy = fmaf( zx, tq, zy);
                    zx = nzx; zy = nzy;
                    Dm *= fmaf(tq, tq, 1.f);
                }
                float m = P * rsqrtf(P * Dm);                // sqrt(P/D), 1 MUFU
                amp = make_float2(zx * m, zy * m);
            }

            // ansatz gate 0 fused with CNOT ring permutation
            float2 a0, a1;
            a0.x = __shfl_sync(FULL, amp.x, src0, 16);
            a0.y = __shfl_sync(FULL, amp.y, src0, 16);
            a1.x = __shfl_sync(FULL, amp.x, src1, 16);
            a1.y = __shfl_sync(FULL, amp.y, src1, 16);

            float2 cur;
            cur.x = g0v0.x*a0.x - g0v0.y*a0.y + g0v1.x*a1.x - g0v1.y*a1.y;
            cur.y = g0v0.x*a0.y + g0v0.y*a0.x + g0v1.x*a1.y + g0v1.y*a1.x;

            // gates 1..3: own/partner coefficient form, no selects
            #pragma unroll
            for (int q = 1; q < NQB; ++q) {
                const int m = 8 >> q;
                float ox = __shfl_xor_sync(FULL, cur.x, m, 16);
                float oy = __shfl_xor_sync(FULL, cur.y, m, 16);
                float2 A = AA[q], B = PB[q];
                float nx = A.x*cur.x - A.y*cur.y + B.x*ox - B.y*oy;
                float ny = A.x*cur.y + A.y*cur.x + B.x*oy + B.y*ox;
                cur.x = nx; cur.y = ny;
            }

            // <Z_q> via 4-level width-16 Walsh-Hadamard, publish per half
            float w0 = cur.x * cur.x + cur.y * cur.y;
            #pragma unroll
            for (int m = 8; m; m >>= 1) {
                float o = __shfl_xor_sync(FULL, w0, m, 16);
                w0 = (il & m) ? (o - w0) : (w0 + o);
            }
            if (isWriterZ) sZ[gate][zj] = w0;
        }
        __syncthreads();

        // ---- 5. projection + LSTM cell (one hidden dim per thread) ----
        float4 zf = *(const float4*)sZ[0];
        float4 zi = *(const float4*)sZ[1];
        float4 zu = *(const float4*)sZ[2];
        float4 zo = *(const float4*)sZ[3];
        float af = fmaf(zf.x, wo0, fmaf(zf.y, wo1, fmaf(zf.z, wo2, fmaf(zf.w, wo3, bo))));
        float ai = fmaf(zi.x, wo0, fmaf(zi.y, wo1, fmaf(zi.z, wo2, fmaf(zi.w, wo3, bo))));
        float ag = fmaf(zu.x, wo0, fmaf(zu.y, wo1, fmaf(zu.z, wo2, fmaf(zu.w, wo3, bo))));
        float ao = fmaf(zo.x, wo0, fmaf(zo.y, wo1, fmaf(zo.z, wo2, fmaf(zo.w, wo3, bo))));
        float f = fmaf(0.5f, tanha(af), 0.5f);
        float i = fmaf(0.5f, tanha(ai), 0.5f);
        float g = tanha(ag + ag);
        float o = fmaf(0.5f, tanha(ao), 0.5f);
        c = fmaf(f, c, i * g);
        h = o * tanha(c);

        *op = h;
        op += HH;
    }

    if (write_tails) {
        size_t base = (size_t)BB * SS * HH;
        out[base + (size_t)b * HH + tid] = h;
        out[base + (size_t)BB * HH + (size_t)b * HH + tid] = c;
    }
}

extern "C" void kernel_launch(void* const* d_in, const int* in_sizes, int n_in,
                              void* d_out, int out_size) {
    const float* x     = (const float*)d_in[0];
    const float* W_in  = (const float*)d_in[1];
    const float* b_in  = (const float*)d_in[2];
    const float* W_out = (const float*)d_in[3];
    const float* b_out = (const float*)d_in[4];
    const float* w_f   = (const float*)d_in[5];
    const float* w_i   = (const float*)d_in[6];
    const float* w_u   = (const float*)d_in[7];
    const float* w_o   = (const float*)d_in[8];
    float* out = (float*)d_out;

    int need_tail = (size_t)out_size >= (size_t)BB * SS * HH + 2 * (size_t)BB * HH;
    qlstm_kernel<<<BB, HH>>>(x, W_in, b_in, W_out, b_out,
                             w_f, w_i, w_u, w_o, out, need_tail);
}